// round 16
// baseline (speedup 1.0000x reference)
#include <cuda_runtime.h>
#include <math.h>
#include <stdint.h>

#define TT   4096
#define HD   512
#define NC   4880
#define G3   1536
#define CLN  16      // scan cluster size = grid size (all-to-all DSMEM)

// ---------------- scratch (static device globals; no allocation) ----------------
__device__ float g_visit[(size_t)TT * HD];          // 8 MB
__device__ float g_gi[(size_t)TT * G3];             // 24 MB
__device__ float g_hs[(size_t)TT * HD];             // 8 MB
__device__ float g_logits[TT];
__device__ float g_alpha[TT];
__device__ float g_part[64 * HD];

// ---------------- f32x2 helpers (SASS FFMA2 — PTX-only, ptxas never fuses) ------
__device__ __forceinline__ unsigned long long pk2(float x, float y) {
    unsigned long long r;
    asm("mov.b64 %0, {%1, %2};" : "=l"(r) : "f"(x), "f"(y));
    return r;
}
__device__ __forceinline__ void upk2(unsigned long long p, float& x, float& y) {
    asm("mov.b64 {%0, %1}, %2;" : "=f"(x), "=f"(y) : "l"(p));
}
__device__ __forceinline__ void fma2(unsigned long long& d,
                                     unsigned long long a, unsigned long long b) {
    asm("fma.rn.f32x2 %0, %1, %2, %3;" : "=l"(d) : "l"(a), "l"(b), "l"(d));
}

// ---------------- Phase 1: visit_emb = H^T @ X_emb  (4096x512, K=4880) ----------
__global__ void __launch_bounds__(256) k_visit(const float* __restrict__ H,
                                               const float* __restrict__ X) {
    __shared__ float sA[8][132];   // [k][t]
    __shared__ float sB[8][132];   // [k][v]
    const int tid = threadIdx.x;
    const int t0 = blockIdx.y << 7, v0 = blockIdx.x << 7;
    const int lk = tid >> 5;            // 0..7
    const int lc = (tid & 31) << 2;     // 0..124
    const int ty = tid >> 4;            // 0..15
    const int tx = tid & 15;

    unsigned long long acc2[8][4];
#pragma unroll
    for (int i = 0; i < 8; i++)
#pragma unroll
        for (int jj = 0; jj < 4; jj++) acc2[i][jj] = pk2(0.f, 0.f);

    const float* pa = H + (size_t)lk * TT + t0 + lc;
    const float* pb = X + (size_t)lk * HD + v0 + lc;
    float4 an = *(const float4*)pa;
    float4 bn = *(const float4*)pb;

    for (int c0 = 0; c0 < NC; c0 += 8) {
        *(float4*)&sA[lk][lc] = an;
        *(float4*)&sB[lk][lc] = bn;
        __syncthreads();
        if (c0 + 8 < NC) {
            pa += (size_t)8 * TT;
            pb += (size_t)8 * HD;
            an = *(const float4*)pa;
            bn = *(const float4*)pb;
        }
#pragma unroll
        for (int k = 0; k < 8; k++) {
            float a[8];
            float4 a0 = *(const float4*)&sA[k][ty << 2];
            float4 a1 = *(const float4*)&sA[k][(ty << 2) + 64];
            float4 b0 = *(const float4*)&sB[k][tx << 2];
            float4 b1 = *(const float4*)&sB[k][(tx << 2) + 64];
            a[0]=a0.x; a[1]=a0.y; a[2]=a0.z; a[3]=a0.w;
            a[4]=a1.x; a[5]=a1.y; a[6]=a1.z; a[7]=a1.w;
            unsigned long long bb[4];
            bb[0] = pk2(b0.x, b0.y); bb[1] = pk2(b0.z, b0.w);
            bb[2] = pk2(b1.x, b1.y); bb[3] = pk2(b1.z, b1.w);
#pragma unroll
            for (int i = 0; i < 8; i++) {
                const unsigned long long aa = pk2(a[i], a[i]);
#pragma unroll
                for (int jj = 0; jj < 4; jj++) fma2(acc2[i][jj], aa, bb[jj]);
            }
        }
        __syncthreads();
    }
#pragma unroll
    for (int i = 0; i < 8; i++) {
        int row = t0 + (ty << 2) + (i & 3) + ((i >= 4) ? 64 : 0);
        float4 o0, o1;
        upk2(acc2[i][0], o0.x, o0.y); upk2(acc2[i][1], o0.z, o0.w);
        upk2(acc2[i][2], o1.x, o1.y); upk2(acc2[i][3], o1.z, o1.w);
        *(float4*)&g_visit[(size_t)row * HD + v0 + (tx << 2)]      = o0;
        *(float4*)&g_visit[(size_t)row * HD + v0 + (tx << 2) + 64] = o1;
    }
}

// ---------------- Phase 2: gi = visit_emb @ W_ih^T + b_ih  (4096x1536, K=512) ---
__global__ void __launch_bounds__(256) k_gi(const float* __restrict__ W,
                                            const float* __restrict__ bih) {
    __shared__ float sA[8][132];   // [k][t]
    __shared__ float sB[8][132];   // [k][r]
    const int tid = threadIdx.x;
    const int t0 = blockIdx.y << 7, r0 = blockIdx.x << 7;
    const int lr = tid >> 1;            // 0..127 (row within tile)
    const int lk = (tid & 1) << 2;      // 0 or 4
    const int ty = tid >> 4;            // 0..15
    const int tx = tid & 15;

    unsigned long long acc2[8][4];
#pragma unroll
    for (int i = 0; i < 8; i++)
#pragma unroll
        for (int jj = 0; jj < 4; jj++) acc2[i][jj] = pk2(0.f, 0.f);

    const float* pa = g_visit + (size_t)(t0 + lr) * HD + lk;
    const float* pb = W + (size_t)(r0 + lr) * HD + lk;
    float4 an = *(const float4*)pa;
    float4 bn = *(const float4*)pb;

    for (int k0 = 0; k0 < HD; k0 += 8) {
        sA[lk + 0][lr] = an.x; sA[lk + 1][lr] = an.y;
        sA[lk + 2][lr] = an.z; sA[lk + 3][lr] = an.w;
        sB[lk + 0][lr] = bn.x; sB[lk + 1][lr] = bn.y;
        sB[lk + 2][lr] = bn.z; sB[lk + 3][lr] = bn.w;
        __syncthreads();
        if (k0 + 8 < HD) {
            pa += 8;
            pb += 8;
            an = *(const float4*)pa;
            bn = *(const float4*)pb;
        }
#pragma unroll
        for (int k = 0; k < 8; k++) {
            float a[8];
            float4 a0 = *(const float4*)&sA[k][ty << 2];
            float4 a1 = *(const float4*)&sA[k][(ty << 2) + 64];
            float4 b0 = *(const float4*)&sB[k][tx << 2];
            float4 b1 = *(const float4*)&sB[k][(tx << 2) + 64];
            a[0]=a0.x; a[1]=a0.y; a[2]=a0.z; a[3]=a0.w;
            a[4]=a1.x; a[5]=a1.y; a[6]=a1.z; a[7]=a1.w;
            unsigned long long bb[4];
            bb[0] = pk2(b0.x, b0.y); bb[1] = pk2(b0.z, b0.w);
            bb[2] = pk2(b1.x, b1.y); bb[3] = pk2(b1.z, b1.w);
#pragma unroll
            for (int i = 0; i < 8; i++) {
                const unsigned long long aa = pk2(a[i], a[i]);
#pragma unroll
                for (int jj = 0; jj < 4; jj++) fma2(acc2[i][jj], aa, bb[jj]);
            }
        }
        __syncthreads();
    }
    const float4 bb0 = *(const float4*)&bih[r0 + (tx << 2)];
    const float4 bb1 = *(const float4*)&bih[r0 + (tx << 2) + 64];
#pragma unroll
    for (int i = 0; i < 8; i++) {
        int row = t0 + (ty << 2) + (i & 3) + ((i >= 4) ? 64 : 0);
        float4 o0, o1;
        upk2(acc2[i][0], o0.x, o0.y); upk2(acc2[i][1], o0.z, o0.w);
        upk2(acc2[i][2], o1.x, o1.y); upk2(acc2[i][3], o1.z, o1.w);
        o0.x += bb0.x; o0.y += bb0.y; o0.z += bb0.z; o0.w += bb0.w;
        o1.x += bb1.x; o1.y += bb1.y; o1.z += bb1.z; o1.w += bb1.w;
        *(float4*)&g_gi[(size_t)row * G3 + r0 + (tx << 2)]      = o0;
        *(float4*)&g_gi[(size_t)row * G3 + r0 + (tx << 2) + 64] = o1;
    }
}

// ---------------- Phase 3: GRU scan — cluster-16, st.async fused delivery -------
// Same proven structure as R14. Two critical-path-only changes:
//  (1) every lane loads its own gi triple directly (lanes with equal q share
//      sectors -> broadcast coalescing; SAME 3 LDG instructions per warp as the
//      old predicated form) — removes the 3 post-reduce broadcast shfls from
//      the serial path into the gates. Values identical -> bitwise-same output.
//  (2) the g_hs bookkeeping store moves AFTER the st.async sends, so the
//      fabric launch (which every consumer waits on) happens first.
__global__ void __launch_bounds__(256, 1) __cluster_dims__(CLN, 1, 1)
k_scan(const float* __restrict__ Whh, const float* __restrict__ bhh) {
    const int b = blockIdx.x, tid = threadIdx.x;
    const int w = tid >> 5, l = tid & 31;
    const int q = l & 3;                     // which of the warp's 4 outputs
    const int j0 = (b << 5) + (w << 2);
    const int jo = j0 + q;

    // weights: wv2[rr*8+m] = {Whh[row][64m+2l], Whh[row][64m+2l+1]},
    // rr = gate*4 + out  (gate 0=r,1=z,2=n; out 0..3)
    unsigned long long wv2[96];
#pragma unroll
    for (int rr = 0; rr < 12; rr++) {
        const size_t row = (size_t)(rr >> 2) * HD + j0 + (rr & 3);
#pragma unroll
        for (int m = 0; m < 8; m++) {
            const float2 v = *(const float2*)(Whh + row * HD + (m << 6) + (l << 1));
            wv2[rr * 8 + m] = pk2(v.x, v.y);
        }
    }
    const float br  = bhh[jo];
    const float bz  = bhh[HD + jo];
    const float bnn = bhh[2 * HD + jo];

    __shared__ __align__(16) float sh[2][HD];       // h double buffer
    __shared__ __align__(8) unsigned long long mbar[2];

    const uint32_t mb0 = (uint32_t)__cvta_generic_to_shared(&mbar[0]);
    const uint32_t mb1 = (uint32_t)__cvta_generic_to_shared(&mbar[1]);
    if (tid == 0) {
        asm volatile("mbarrier.init.shared.b64 [%0], %1;" :: "r"(mb0), "r"(1) : "memory");
        asm volatile("mbarrier.init.shared.b64 [%0], %1;" :: "r"(mb1), "r"(1) : "memory");
        // arm: mbar[1] completes for step 1, mbar[0] for step 2 (2048B each)
        asm volatile("mbarrier.arrive.expect_tx.shared.b64 _, [%0], %1;"
                     :: "r"(mb1), "r"(2048u) : "memory");
        asm volatile("mbarrier.arrive.expect_tx.shared.b64 _, [%0], %1;"
                     :: "r"(mb0), "r"(2048u) : "memory");
    }
    for (int i = tid; i < HD; i += 256) sh[0][i] = 0.f;   // h(-1) = 0
    __syncthreads();
    // all CTAs' mbarriers init+armed visible cluster-wide before any st.async
    asm volatile("barrier.cluster.arrive.aligned;" ::: "memory");
    asm volatile("barrier.cluster.wait.aligned;" ::: "memory");

    int par0 = 0, par1 = 0;   // parity per mbarrier, flip after each wait

    for (int t = 0; t < TT; t++) {
        const int p = t & 1;

        // prefetch this lane's gi triple (independent of h; overlaps the wait;
        // lanes sharing q hit the same sectors -> broadcast coalescing)
        float ir, iz, in_;
        {
            const float* g = g_gi + (size_t)t * G3 + jo;
            ir  = g[0];
            iz  = g[HD];
            in_ = g[2 * HD];
        }

        if (t > 0) {
            const uint32_t mb = p ? mb1 : mb0;
            const int par = p ? par1 : par0;
            unsigned done;
            do {
                asm volatile(
                    "{\n\t"
                    ".reg .pred P;\n\t"
                    "mbarrier.try_wait.parity.acquire.cluster.shared::cta.b64 "
                    "P, [%1], %2, 0x989680;\n\t"
                    "selp.b32 %0, 1, 0, P;\n\t"
                    "}"
                    : "=r"(done) : "r"(mb), "r"(par) : "memory");
            } while (!done);
            if (p) par1 ^= 1; else par0 ^= 1;
            // re-arm this mbarrier for its next phase (step t+2)
            if (tid == 0)
                asm volatile("mbarrier.arrive.expect_tx.shared.b64 _, [%0], %1;"
                             :: "r"(mb), "r"(2048u) : "memory");
        }

        const float* S = sh[p];
        unsigned long long A2[12];
#pragma unroll
        for (int rr = 0; rr < 12; rr++) A2[rr] = pk2(0.f, 0.f);
        const unsigned long long* S2 = (const unsigned long long*)S;
#pragma unroll
        for (int m = 0; m < 8; m++) {
            const unsigned long long hv = S2[(m << 5) + l];
#pragma unroll
            for (int rr = 0; rr < 12; rr++) fma2(A2[rr], wv2[rr * 8 + m], hv);
        }
        float A[12];
#pragma unroll
        for (int rr = 0; rr < 12; rr++) {
            float x, y;
            upk2(A2[rr], x, y);
            A[rr] = x + y;
        }
        // stage 1: sum 4-lane clusters for all 12 accs
#pragma unroll
        for (int rr = 0; rr < 12; rr++) {
            A[rr] += __shfl_xor_sync(0xffffffffu, A[rr], 1);
            A[rr] += __shfl_xor_sync(0xffffffffu, A[rr], 2);
        }
        // stage 2: keep own gate triple, finish over the 8 clusters
        float ar = A[q], az = A[4 + q], an = A[8 + q];
#pragma unroll
        for (int o = 4; o <= 16; o <<= 1) {
            ar += __shfl_xor_sync(0xffffffffu, ar, o);
            az += __shfl_xor_sync(0xffffffffu, az, o);
            an += __shfl_xor_sync(0xffffffffu, an, o);
        }
        // gates: sigmoid(x) = 0.5 + 0.5*tanh(0.5x) (identical math, no div.rn)
        const float r  = 0.5f + 0.5f * tanhf(0.5f * (ir + ar + br));
        const float z  = 0.5f + 0.5f * tanhf(0.5f * (iz + az + bz));
        const float n  = tanhf(in_ + r * (an + bnn));
        const float hn = (1.f - z) * n + z * S[jo];

        if (t + 1 < TT) {
            // pack the warp's 4 outputs onto its q==0 lanes (h(j0..j0+3))
            const float h1 = __shfl_down_sync(0xffffffffu, hn, 1);
            const float h2 = __shfl_down_sync(0xffffffffu, hn, 2);
            const float h3 = __shfl_down_sync(0xffffffffu, hn, 3);
            if (q == 0) {
                const unsigned long long v0 = pk2(hn, h1);
                const unsigned long long v1 = pk2(h2, h3);
                const uint32_t laddr =
                    (uint32_t)__cvta_generic_to_shared(&sh[p ^ 1][j0]);
                const uint32_t mbn = (p ^ 1) ? mb1 : mb0;
                const int r1 = l >> 2;      // q0 lanes: l=0,4..28 -> r1=0..7
                // one fused store+signal per rank (r1 and r1+8)
                asm volatile(
                    "{\n\t"
                    ".reg .b32 ra, rb;\n\t"
                    "mapa.shared::cluster.u32 ra, %0, %1;\n\t"
                    "mapa.shared::cluster.u32 rb, %2, %1;\n\t"
                    "st.async.weak.shared::cluster.mbarrier::complete_tx::bytes"
                    ".v2.b64 [ra], {%3, %4}, [rb];\n\t"
                    "}" :: "r"(laddr), "r"(r1), "r"(mbn),
                           "l"(v0), "l"(v1) : "memory");
                asm volatile(
                    "{\n\t"
                    ".reg .b32 ra, rb;\n\t"
                    "mapa.shared::cluster.u32 ra, %0, %1;\n\t"
                    "mapa.shared::cluster.u32 rb, %2, %1;\n\t"
                    "st.async.weak.shared::cluster.mbarrier::complete_tx::bytes"
                    ".v2.b64 [ra], {%3, %4}, [rb];\n\t"
                    "}" :: "r"(laddr), "r"(r1 + 8), "r"(mbn),
                           "l"(v0), "l"(v1) : "memory");
            }
        }
        // bookkeeping store AFTER the fabric launch (off the consumer path)
        if (l < 4) g_hs[(size_t)t * HD + jo] = hn;
    }
}

// ---------------- Phase 4: attention pooling ------------------------------------
__global__ void k_logits(const float* __restrict__ watt) {
    const int wp = threadIdx.x >> 5, l = threadIdx.x & 31;
    const int t = (blockIdx.x << 3) + wp;
    const float* hr = g_hs + (size_t)t * HD;
    float s = 0.f;
#pragma unroll
    for (int m = 0; m < 16; m++) {
        int k = l + (m << 5);
        s += hr[k] * watt[k];
    }
#pragma unroll
    for (int o = 16; o; o >>= 1) s += __shfl_down_sync(0xffffffffu, s, o);
    if (l == 0) g_logits[t] = s;
}

__global__ void k_softmax() {
    __shared__ float sred[16];
    const int tid = threadIdx.x;   // 512 threads, 8 logits each
    float v[8];
    float mx = -3.402823466e38f;
#pragma unroll
    for (int i = 0; i < 8; i++) {
        v[i] = g_logits[tid + (i << 9)];
        mx = fmaxf(mx, v[i]);
    }
#pragma unroll
    for (int o = 16; o; o >>= 1) mx = fmaxf(mx, __shfl_xor_sync(0xffffffffu, mx, o));
    if ((tid & 31) == 0) sred[tid >> 5] = mx;
    __syncthreads();
    if (tid == 0) {
        float m = sred[0];
        for (int i = 1; i < 16; i++) m = fmaxf(m, sred[i]);
        sred[0] = m;
    }
    __syncthreads();
    const float m = sred[0];
    __syncthreads();
    float s = 0.f;
#pragma unroll
    for (int i = 0; i < 8; i++) {
        v[i] = expf(v[i] - m);
        s += v[i];
    }
#pragma unroll
    for (int o = 16; o; o >>= 1) s += __shfl_xor_sync(0xffffffffu, s, o);
    if ((tid & 31) == 0) sred[tid >> 5] = s;
    __syncthreads();
    if (tid == 0) {
        float S = 0.f;
        for (int i = 0; i < 16; i++) S += sred[i];
        sred[0] = S;
    }
    __syncthreads();
    const float inv = 1.f / sred[0];
#pragma unroll
    for (int i = 0; i < 8; i++) g_alpha[tid + (i << 9)] = v[i] * inv;
}

__global__ void k_wsum() {
    const int j = threadIdx.x, b = blockIdx.x;   // 64 blocks x 512 threads
    float acc = 0.f;
    const int t0 = b << 6;
    for (int t = t0; t < t0 + 64; t++)
        acc += g_alpha[t] * g_hs[(size_t)t * HD + j];
    g_part[b * HD + j] = acc;
}

__global__ void k_final(float* __restrict__ out) {
    const int j = threadIdx.x;
    float a = 0.f;
    for (int b = 0; b < 64; b++) a += g_part[b * HD + j];
    out[j] = a;
}

// ---------------- launch --------------------------------------------------------
extern "C" void kernel_launch(void* const* d_in, const int* in_sizes, int n_in,
                              void* d_out, int out_size) {
    const float* H    = (const float*)d_in[0];
    // d_in[1] = TE (unused by reference)
    const float* X    = (const float*)d_in[2];
    const float* Wih  = (const float*)d_in[3];
    const float* Whh  = (const float*)d_in[4];
    const float* bih  = (const float*)d_in[5];
    const float* bhh  = (const float*)d_in[6];
    const float* watt = (const float*)d_in[7];
    float* out = (float*)d_out;

    // cluster size 16 > portable max 8: opt in (host attr, graph-capture safe)
    cudaFuncSetAttribute((const void*)k_scan,
                         cudaFuncAttributeNonPortableClusterSizeAllowed, 1);

    k_visit<<<dim3(HD / 128, TT / 128), 256>>>(H, X);
    k_gi<<<dim3(G3 / 128, TT / 128), 256>>>(Wih, bih);
    k_scan<<<CLN, 256>>>(Whh, bhh);       // cluster dims from __cluster_dims__
    k_logits<<<TT / 8, 256>>>(watt);
    k_softmax<<<1, 512>>>();
    k_wsum<<<64, 512>>>();
    k_final<<<1, 512>>>(out);
}